// round 8
// baseline (speedup 1.0000x reference)
#include <cuda_runtime.h>

// Problem shape (fixed by dataset): 100000 nodes, 3.2M edges, 256 -> 32 -> 16x2
#define F0 256
#define F1 32
#define F2 16
#define MAXN 100000
#define MAXE 3200000
#define CSRMAX (MAXE + 31 * MAXN)   // padded-CSR worst case: 6.3M records
#define KT 32
#define GROWS 256
#define SCAN_BLK 1024
#define NBSUM 128         // >= nb = ceil(MAXN/SCAN_BLK) = 98
#define GEMMB 391         // gemm tiles = ceil(100000/256)

// Scratch (allocation-free rule: __device__ globals)
__device__ __align__(16) float  g_dinv[MAXN];
__device__ int    g_degcnt[MAXN];
__device__ int    g_off[MAXN + 1];
__device__ int    g_cursor[MAXN];
__device__ int    g_bsum[NBSUM];
__device__ __align__(16) float2 g_csr[CSRMAX];   // (src bits, weight), 32-padded
__device__ __align__(16) float  g_hx[MAXN * F1];
__device__ __align__(16) float  g_h [MAXN * F1];

// ---------------------------------------------------------------------------
__global__ void zero_kernel(int n) {
    int i = blockIdx.x * blockDim.x + threadIdx.x;
    if (i < n) g_degcnt[i] = 0;
}

// in-degree over dst = edge_index[1], 4 edges per thread via int4
__global__ void deg_kernel(const int* __restrict__ ei, int E) {
    int e = (blockIdx.x * blockDim.x + threadIdx.x) * 4;
    if (e + 3 < E) {
        int4 d = *reinterpret_cast<const int4*>(ei + E + e);
        atomicAdd(&g_degcnt[d.x], 1);
        atomicAdd(&g_degcnt[d.y], 1);
        atomicAdd(&g_degcnt[d.z], 1);
        atomicAdd(&g_degcnt[d.w], 1);
    } else {
        for (int k = e; k < E; k++) atomicAdd(&g_degcnt[ei[E + k]], 1);
    }
}

// ---- scan1: per-block exclusive scan of PADDED degrees (shuffle) + dinv ---
__global__ void __launch_bounds__(SCAN_BLK) scan1_kernel(int n) {
    __shared__ int ws[32];
    int tid = threadIdx.x;
    int i = blockIdx.x * SCAN_BLK + tid;
    int lane = tid & 31, wid = tid >> 5;
    int deg = (i < n) ? g_degcnt[i] : 0;
    if (i < n) g_dinv[i] = rsqrtf((float)deg + 1.0f);
    int v = (deg + 31) & ~31;                     // padded degree
    int s = v;
#pragma unroll
    for (int o = 1; o < 32; o <<= 1) {
        int u = __shfl_up_sync(0xffffffffu, s, o);
        if (lane >= o) s += u;
    }
    if (lane == 31) ws[wid] = s;
    __syncthreads();
    if (wid == 0) {
        int t = ws[lane];
#pragma unroll
        for (int o = 1; o < 32; o <<= 1) {
            int u = __shfl_up_sync(0xffffffffu, t, o);
            if (lane >= o) t += u;
        }
        ws[lane] = t;
    }
    __syncthreads();
    int pre = wid ? ws[wid - 1] : 0;
    if (i < n) g_off[i] = s - v + pre;            // exclusive within block
    if (tid == 0) g_bsum[blockIdx.x] = ws[31];    // block total (padded)
}

// ---- scan3: redundant per-block scan of block sums + finalize offsets -----
__global__ void __launch_bounds__(256) scan3_kernel(int n, int nb) {
    __shared__ int ws[8];
    __shared__ int sp[NBSUM];
    int tid = threadIdx.x;
    int lane = tid & 31, wid = tid >> 5;
    int v = (tid < nb) ? g_bsum[tid] : 0;
    int s = v;
#pragma unroll
    for (int o = 1; o < 32; o <<= 1) {
        int u = __shfl_up_sync(0xffffffffu, s, o);
        if (lane >= o) s += u;
    }
    if (lane == 31) ws[wid] = s;
    __syncthreads();
    if (wid == 0) {
        int t = (lane < 8) ? ws[lane] : 0;
#pragma unroll
        for (int o = 1; o < 8; o <<= 1) {
            int u = __shfl_up_sync(0xffffffffu, t, o);
            if (lane >= o) t += u;
        }
        if (lane < 8) ws[lane] = t;
    }
    __syncthreads();
    if (tid < nb) sp[tid] = s - v + (wid ? ws[wid - 1] : 0);  // exclusive
    __syncthreads();

    int i = blockIdx.x * 256 + tid;
    if (i < n) {
        int o = g_off[i] + sp[i >> 10];
        g_off[i] = o;
        g_cursor[i] = o;
    }
    if (i == 0) g_off[n] = sp[nb - 1] + g_bsum[nb - 1];   // padded total
}

// ---------------------------------------------------------------------------
// Fused: blocks [0, GEMMB) do hx = x @ W1 (register-tiled, proven);
//        blocks [GEMMB, grid) do CSR fill + zero pad-tails.
__global__ void __launch_bounds__(256) gemmfill_kernel(
        const float* __restrict__ x, const float* __restrict__ W1,
        const int* __restrict__ ei, int n, int E, int fillb) {
    if (blockIdx.x >= GEMMB) {
        int t = (blockIdx.x - GEMMB) * 256 + threadIdx.x;
        int stride = fillb * 256;
        for (int e = t; e < E; e += stride) {
            int src = ei[e];
            int dst = ei[E + e];
            int pos = atomicAdd(&g_cursor[dst], 1);
            g_csr[pos] = make_float2(__int_as_float(src),
                                     g_dinv[src] * g_dinv[dst]);
        }
        // zero pad-tails: slots [off+deg, off+pdeg) per node (disjoint from
        // filled slots; no ordering needed)
        for (int node = t; node < n; node += stride) {
            int beg = g_off[node] + g_degcnt[node];
            int end = g_off[node + 1];
            float2 z = make_float2(__int_as_float(0), 0.f);
            for (int p = beg; p < end; p++) g_csr[p] = z;
        }
        return;
    }
    // ---- GEMM tile ----
    __shared__ float xs[GROWS * (KT + 1)];
    __shared__ float Wts[KT * F1];

    int tid = threadIdx.x;
    int cg = tid & 3;
    int rg = tid >> 2;
    int row0 = blockIdx.x * GROWS;

    float acc[4][8];
#pragma unroll
    for (int i = 0; i < 4; i++)
#pragma unroll
        for (int j = 0; j < 8; j++) acc[i][j] = 0.0f;

    for (int kt = 0; kt < F0; kt += KT) {
        __syncthreads();
        {
            float4 w = *reinterpret_cast<const float4*>(W1 + (size_t)kt * F1 + tid * 4);
            *reinterpret_cast<float4*>(&Wts[tid * 4]) = w;
        }
#pragma unroll
        for (int it = 0; it < 8; it++) {
            int i = tid + it * 256;
            int r = i >> 3;
            int q = i & 7;
            int grow = row0 + r;
            float4 v = make_float4(0.f, 0.f, 0.f, 0.f);
            if (grow < n)
                v = *reinterpret_cast<const float4*>(x + (size_t)grow * F0 + kt + q * 4);
            float* dst = &xs[r * (KT + 1) + q * 4];
            dst[0] = v.x; dst[1] = v.y; dst[2] = v.z; dst[3] = v.w;
        }
        __syncthreads();

#pragma unroll
        for (int k = 0; k < KT; k++) {
            float xv[4];
#pragma unroll
            for (int i = 0; i < 4; i++)
                xv[i] = xs[(rg * 4 + i) * (KT + 1) + k];
            float4 w0 = *reinterpret_cast<const float4*>(&Wts[k * F1 + cg * 8]);
            float4 w1 = *reinterpret_cast<const float4*>(&Wts[k * F1 + cg * 8 + 4]);
#pragma unroll
            for (int i = 0; i < 4; i++) {
                acc[i][0] = fmaf(xv[i], w0.x, acc[i][0]);
                acc[i][1] = fmaf(xv[i], w0.y, acc[i][1]);
                acc[i][2] = fmaf(xv[i], w0.z, acc[i][2]);
                acc[i][3] = fmaf(xv[i], w0.w, acc[i][3]);
                acc[i][4] = fmaf(xv[i], w1.x, acc[i][4]);
                acc[i][5] = fmaf(xv[i], w1.y, acc[i][5]);
                acc[i][6] = fmaf(xv[i], w1.z, acc[i][6]);
                acc[i][7] = fmaf(xv[i], w1.w, acc[i][7]);
            }
        }
    }

#pragma unroll
    for (int i = 0; i < 4; i++) {
        int row = row0 + rg * 4 + i;
        if (row < n) {
            float* dst = &g_hx[(size_t)row * F1 + cg * 8];
            *reinterpret_cast<float4*>(dst) =
                make_float4(acc[i][0], acc[i][1], acc[i][2], acc[i][3]);
            *reinterpret_cast<float4*>(dst + 4) =
                make_float4(acc[i][4], acc[i][5], acc[i][6], acc[i][7]);
        }
    }
}

// ---------------------------------------------------------------------------
// Gather core — padded CSR: every segment is a multiple of 32, so ONLY the
// proven fully-unrolled tile loop remains (compile-time shfl lanes, 2 accs).
__device__ __forceinline__ float gather_node(
        const float* __restrict__ feat, int beg, int end, int lane) {
    float acc0 = 0.f, acc1 = 0.f;
    for (int k = beg; k < end; k += 32) {
        float2 rec = g_csr[k + lane];
        int   src = __float_as_int(rec.x);
        float w   = rec.y;
#pragma unroll
        for (int j = 0; j < 32; j += 2) {
            int   s0 = __shfl_sync(0xffffffffu, src, j);
            float w0 = __shfl_sync(0xffffffffu, w,   j);
            int   s1 = __shfl_sync(0xffffffffu, src, j + 1);
            float w1 = __shfl_sync(0xffffffffu, w,   j + 1);
            acc0 = fmaf(feat[(size_t)s0 * F1 + lane], w0, acc0);
            acc1 = fmaf(feat[(size_t)s1 * F1 + lane], w1, acc1);
        }
    }
    return acc0 + acc1;
}

// Gather layer 1: one warp per node, lane = feature col.
__global__ void __launch_bounds__(256) gather1_kernel(
        const float* __restrict__ b1, int n) {
    int node = (blockIdx.x * blockDim.x + threadIdx.x) >> 5;
    int lane = threadIdx.x & 31;
    if (node >= n) return;
    int beg = g_off[node];
    int end = g_off[node + 1];
    float acc = gather_node(g_hx, beg, end, lane);
    float d = g_dinv[node];
    float v = acc + g_hx[(size_t)node * F1 + lane] * d * d + b1[lane];
    g_h[(size_t)node * F1 + lane] = v > 0.f ? v : 0.f;
}

// Gather layer 2 + fused mu/sigma epilogue.
__global__ void __launch_bounds__(256) gather2_kernel(
        const float* __restrict__ Wm, const float* __restrict__ bm,
        const float* __restrict__ Wv, const float* __restrict__ bv,
        float* __restrict__ out, int n) {
    __shared__ float Wms[F1 * F2];
    __shared__ float Wvs[F1 * F2];
    __shared__ float ts[8][F1];
    for (int i = threadIdx.x; i < F1 * F2; i += blockDim.x) {
        Wms[i] = Wm[i];
        Wvs[i] = Wv[i];
    }
    __syncthreads();

    int wIn  = threadIdx.x >> 5;
    int lane = threadIdx.x & 31;
    int node = blockIdx.x * 8 + wIn;
    if (node >= n) return;

    int beg = g_off[node];
    int end = g_off[node + 1];
    float acc = gather_node(g_h, beg, end, lane);
    float d = g_dinv[node];
    ts[wIn][lane] = acc + g_h[(size_t)node * F1 + lane] * d * d;
    __syncwarp();

    int c = lane & 15;
    const float* Wp = (lane < 16) ? Wms : Wvs;
    float a = 0.f;
#pragma unroll
    for (int kk = 0; kk < F1; kk++)
        a = fmaf(ts[wIn][kk], Wp[kk * F2 + c], a);
    a += (lane < 16) ? bm[c] : bv[c];
    size_t o = (lane < 16) ? ((size_t)node * F2 + c)
                           : ((size_t)n * F2 + (size_t)node * F2 + c);
    out[o] = a;
}

// ---------------------------------------------------------------------------
extern "C" void kernel_launch(void* const* d_in, const int* in_sizes, int n_in,
                              void* d_out, int out_size) {
    const float* x  = (const float*)d_in[0];
    const int*   ei = (const int*)  d_in[1];
    const float* W1 = (const float*)d_in[2];
    const float* b1 = (const float*)d_in[3];
    const float* Wm = (const float*)d_in[4];
    const float* bm = (const float*)d_in[5];
    const float* Wv = (const float*)d_in[6];
    const float* bv = (const float*)d_in[7];
    float* out = (float*)d_out;

    int n = in_sizes[0] / F0;      // 100000
    int E = in_sizes[1] / 2;       // 3200000
    int nb = (n + SCAN_BLK - 1) / SCAN_BLK;      // 98
    int e4blocks = ((E + 3) / 4 + 255) / 256;
    int fillb = 12109;                            // GEMMB + fillb = 12500

    zero_kernel<<<(n + 255) / 256, 256>>>(n);
    deg_kernel<<<e4blocks, 256>>>(ei, E);
    scan1_kernel<<<nb, SCAN_BLK>>>(n);
    scan3_kernel<<<(n + 255) / 256, 256>>>(n, nb);
    gemmfill_kernel<<<GEMMB + fillb, 256>>>(x, W1, ei, n, E, fillb);
    gather1_kernel<<<(n * 32 + 255) / 256, 256>>>(b1, n);
    gather2_kernel<<<(n + 7) / 8, 256>>>(Wm, bm, Wv, bv, out, n);
}

// round 9
// speedup vs baseline: 1.1718x; 1.1718x over previous
#include <cuda_runtime.h>

// Problem shape (fixed by dataset): 100000 nodes, 3.2M edges, 256 -> 32 -> 16x2
#define F0 256
#define F1 32
#define F2 16
#define MAXN 100000
#define MAXE 3200000
#define KT 32
#define GROWS 256
#define SCAN_BLK 1024
#define NBSUM 128         // >= nb = ceil(MAXN/SCAN_BLK) = 98

// Scratch (allocation-free rule: __device__ globals)
__device__ __align__(16) float  g_dinv[MAXN];
__device__ int    g_degcnt[MAXN];
__device__ int    g_off[MAXN + 1];
__device__ int    g_cursor[MAXN];
__device__ int    g_bsum[NBSUM];
__device__ __align__(16) float2 g_csr[MAXE];     // (src bits, weight)
__device__ __align__(16) float  g_hx[MAXN * F1];
__device__ __align__(16) float  g_h [MAXN * F1];

// ---------------------------------------------------------------------------
__global__ void zero_kernel(int n) {
    int i = blockIdx.x * blockDim.x + threadIdx.x;
    if (i < n) g_degcnt[i] = 0;
}

// in-degree over dst = edge_index[1], 4 edges per thread via int4
__global__ void deg_kernel(const int* __restrict__ ei, int E) {
    int e = (blockIdx.x * blockDim.x + threadIdx.x) * 4;
    if (e + 3 < E) {
        int4 d = *reinterpret_cast<const int4*>(ei + E + e);
        atomicAdd(&g_degcnt[d.x], 1);
        atomicAdd(&g_degcnt[d.y], 1);
        atomicAdd(&g_degcnt[d.z], 1);
        atomicAdd(&g_degcnt[d.w], 1);
    } else {
        for (int k = e; k < E; k++) atomicAdd(&g_degcnt[ei[E + k]], 1);
    }
}

// ---- scan1: per-block exclusive scan of degcnt (shuffle) + dinv -----------
__global__ void __launch_bounds__(SCAN_BLK) scan1_kernel(int n) {
    __shared__ int ws[32];
    int tid = threadIdx.x;
    int i = blockIdx.x * SCAN_BLK + tid;
    int lane = tid & 31, wid = tid >> 5;
    int v = (i < n) ? g_degcnt[i] : 0;
    if (i < n) g_dinv[i] = rsqrtf((float)v + 1.0f);
    int s = v;
#pragma unroll
    for (int o = 1; o < 32; o <<= 1) {
        int u = __shfl_up_sync(0xffffffffu, s, o);
        if (lane >= o) s += u;
    }
    if (lane == 31) ws[wid] = s;
    __syncthreads();
    if (wid == 0) {
        int t = ws[lane];
#pragma unroll
        for (int o = 1; o < 32; o <<= 1) {
            int u = __shfl_up_sync(0xffffffffu, t, o);
            if (lane >= o) t += u;
        }
        ws[lane] = t;
    }
    __syncthreads();
    int pre = wid ? ws[wid - 1] : 0;
    if (i < n) g_off[i] = s - v + pre;            // exclusive within block
    if (tid == 0) g_bsum[blockIdx.x] = ws[31];    // block total
}

// ---- scan3: redundant per-block scan of block sums + finalize offsets -----
__global__ void __launch_bounds__(256) scan3_kernel(int n, int E, int nb) {
    __shared__ int ws[8];
    __shared__ int sp[NBSUM];
    int tid = threadIdx.x;
    int lane = tid & 31, wid = tid >> 5;
    int v = (tid < nb) ? g_bsum[tid] : 0;
    int s = v;
#pragma unroll
    for (int o = 1; o < 32; o <<= 1) {
        int u = __shfl_up_sync(0xffffffffu, s, o);
        if (lane >= o) s += u;
    }
    if (lane == 31) ws[wid] = s;
    __syncthreads();
    if (wid == 0) {
        int t = (lane < 8) ? ws[lane] : 0;
#pragma unroll
        for (int o = 1; o < 8; o <<= 1) {
            int u = __shfl_up_sync(0xffffffffu, t, o);
            if (lane >= o) t += u;
        }
        if (lane < 8) ws[lane] = t;
    }
    __syncthreads();
    if (tid < nb) sp[tid] = s - v + (wid ? ws[wid - 1] : 0);  // exclusive
    __syncthreads();

    int i = blockIdx.x * 256 + tid;
    if (i < n) {
        int o = g_off[i] + sp[i >> 10];
        g_off[i] = o;
        g_cursor[i] = o;
    }
    if (i == 0) g_off[n] = E;
}

// ---- CSR fill: 1 edge per thread (proven round-3 config) ------------------
__global__ void fill_kernel(const int* __restrict__ ei, int E) {
    int e = blockIdx.x * blockDim.x + threadIdx.x;
    if (e >= E) return;
    int src = ei[e];
    int dst = ei[E + e];
    int pos = atomicAdd(&g_cursor[dst], 1);
    g_csr[pos] = make_float2(__int_as_float(src), g_dinv[src] * g_dinv[dst]);
}

// ---------------------------------------------------------------------------
// hx = x @ W1  (N x 256  @  256 x 32), register-tiled (proven).
__global__ void __launch_bounds__(256) gemm1_kernel(
        const float* __restrict__ x, const float* __restrict__ W1, int n) {
    __shared__ float xs[GROWS * (KT + 1)];
    __shared__ float Wts[KT * F1];

    int tid = threadIdx.x;
    int cg = tid & 3;
    int rg = tid >> 2;
    int row0 = blockIdx.x * GROWS;

    float acc[4][8];
#pragma unroll
    for (int i = 0; i < 4; i++)
#pragma unroll
        for (int j = 0; j < 8; j++) acc[i][j] = 0.0f;

    for (int kt = 0; kt < F0; kt += KT) {
        __syncthreads();
        {
            float4 w = *reinterpret_cast<const float4*>(W1 + (size_t)kt * F1 + tid * 4);
            *reinterpret_cast<float4*>(&Wts[tid * 4]) = w;
        }
#pragma unroll
        for (int it = 0; it < 8; it++) {
            int i = tid + it * 256;
            int r = i >> 3;
            int q = i & 7;
            int grow = row0 + r;
            float4 v = make_float4(0.f, 0.f, 0.f, 0.f);
            if (grow < n)
                v = *reinterpret_cast<const float4*>(x + (size_t)grow * F0 + kt + q * 4);
            float* dst = &xs[r * (KT + 1) + q * 4];
            dst[0] = v.x; dst[1] = v.y; dst[2] = v.z; dst[3] = v.w;
        }
        __syncthreads();

#pragma unroll
        for (int k = 0; k < KT; k++) {
            float xv[4];
#pragma unroll
            for (int i = 0; i < 4; i++)
                xv[i] = xs[(rg * 4 + i) * (KT + 1) + k];
            float4 w0 = *reinterpret_cast<const float4*>(&Wts[k * F1 + cg * 8]);
            float4 w1 = *reinterpret_cast<const float4*>(&Wts[k * F1 + cg * 8 + 4]);
#pragma unroll
            for (int i = 0; i < 4; i++) {
                acc[i][0] = fmaf(xv[i], w0.x, acc[i][0]);
                acc[i][1] = fmaf(xv[i], w0.y, acc[i][1]);
                acc[i][2] = fmaf(xv[i], w0.z, acc[i][2]);
                acc[i][3] = fmaf(xv[i], w0.w, acc[i][3]);
                acc[i][4] = fmaf(xv[i], w1.x, acc[i][4]);
                acc[i][5] = fmaf(xv[i], w1.y, acc[i][5]);
                acc[i][6] = fmaf(xv[i], w1.z, acc[i][6]);
                acc[i][7] = fmaf(xv[i], w1.w, acc[i][7]);
            }
        }
    }

#pragma unroll
    for (int i = 0; i < 4; i++) {
        int row = row0 + rg * 4 + i;
        if (row < n) {
            float* dst = &g_hx[(size_t)row * F1 + cg * 8];
            *reinterpret_cast<float4*>(dst) =
                make_float4(acc[i][0], acc[i][1], acc[i][2], acc[i][3]);
            *reinterpret_cast<float4*>(dst + 4) =
                make_float4(acc[i][4], acc[i][5], acc[i][6], acc[i][7]);
        }
    }
}

// ---------------------------------------------------------------------------
// Gather core — proven round-3 inner loop.
__device__ __forceinline__ float gather_node(
        const float* __restrict__ feat, int beg, int end, int lane) {
    float acc0 = 0.f, acc1 = 0.f;
    int k = beg;
    for (; k + 32 <= end; k += 32) {
        float2 rec = g_csr[k + lane];
        int   src = __float_as_int(rec.x);
        float w   = rec.y;
#pragma unroll
        for (int j = 0; j < 32; j += 2) {
            int   s0 = __shfl_sync(0xffffffffu, src, j);
            float w0 = __shfl_sync(0xffffffffu, w,   j);
            int   s1 = __shfl_sync(0xffffffffu, src, j + 1);
            float w1 = __shfl_sync(0xffffffffu, w,   j + 1);
            acc0 = fmaf(feat[(size_t)s0 * F1 + lane], w0, acc0);
            acc1 = fmaf(feat[(size_t)s1 * F1 + lane], w1, acc1);
        }
    }
    int rem = end - k;
    if (rem > 0) {
        float2 rec = make_float2(__int_as_float(0), 0.f);
        if (lane < rem) rec = g_csr[k + lane];
        int   src = __float_as_int(rec.x);
        float w   = rec.y;
        for (int j = 0; j < rem; j++) {
            int   s0 = __shfl_sync(0xffffffffu, src, j);
            float w0 = __shfl_sync(0xffffffffu, w,   j);
            acc0 = fmaf(feat[(size_t)s0 * F1 + lane], w0, acc0);
        }
    }
    return acc0 + acc1;
}

// Gather layer 1: one warp per node, lane = feature col.
__global__ void __launch_bounds__(256) gather1_kernel(
        const float* __restrict__ b1, int n) {
    int node = (blockIdx.x * blockDim.x + threadIdx.x) >> 5;
    int lane = threadIdx.x & 31;
    if (node >= n) return;
    int beg = g_off[node];
    int end = g_off[node + 1];
    float acc = gather_node(g_hx, beg, end, lane);
    float d = g_dinv[node];
    float v = acc + g_hx[(size_t)node * F1 + lane] * d * d + b1[lane];
    g_h[(size_t)node * F1 + lane] = v > 0.f ? v : 0.f;
}

// Gather layer 2 + fused mu/sigma epilogue.
__global__ void __launch_bounds__(256) gather2_kernel(
        const float* __restrict__ Wm, const float* __restrict__ bm,
        const float* __restrict__ Wv, const float* __restrict__ bv,
        float* __restrict__ out, int n) {
    __shared__ float Wms[F1 * F2];
    __shared__ float Wvs[F1 * F2];
    __shared__ float ts[8][F1];
    for (int i = threadIdx.x; i < F1 * F2; i += blockDim.x) {
        Wms[i] = Wm[i];
        Wvs[i] = Wv[i];
    }
    __syncthreads();

    int wIn  = threadIdx.x >> 5;
    int lane = threadIdx.x & 31;
    int node = blockIdx.x * 8 + wIn;
    if (node >= n) return;

    int beg = g_off[node];
    int end = g_off[node + 1];
    float acc = gather_node(g_h, beg, end, lane);
    float d = g_dinv[node];
    ts[wIn][lane] = acc + g_h[(size_t)node * F1 + lane] * d * d;
    __syncwarp();

    int c = lane & 15;
    const float* Wp = (lane < 16) ? Wms : Wvs;
    float a = 0.f;
#pragma unroll
    for (int kk = 0; kk < F1; kk++)
        a = fmaf(ts[wIn][kk], Wp[kk * F2 + c], a);
    a += (lane < 16) ? bm[c] : bv[c];
    size_t o = (lane < 16) ? ((size_t)node * F2 + c)
                           : ((size_t)n * F2 + (size_t)node * F2 + c);
    out[o] = a;
}

// ---------------------------------------------------------------------------
extern "C" void kernel_launch(void* const* d_in, const int* in_sizes, int n_in,
                              void* d_out, int out_size) {
    // Lazily-created side stream + fork/join events (no device memory involved;
    // work issued is identical on every call -> deterministic & capturable).
    static cudaStream_t s2 = nullptr;
    static cudaEvent_t evFork = nullptr, evJoin = nullptr;
    if (s2 == nullptr) {
        cudaStreamCreateWithFlags(&s2, cudaStreamNonBlocking);
        cudaEventCreateWithFlags(&evFork, cudaEventDisableTiming);
        cudaEventCreateWithFlags(&evJoin, cudaEventDisableTiming);
    }

    const float* x  = (const float*)d_in[0];
    const int*   ei = (const int*)  d_in[1];
    const float* W1 = (const float*)d_in[2];
    const float* b1 = (const float*)d_in[3];
    const float* Wm = (const float*)d_in[4];
    const float* bm = (const float*)d_in[5];
    const float* Wv = (const float*)d_in[6];
    const float* bv = (const float*)d_in[7];
    float* out = (float*)d_out;

    int n = in_sizes[0] / F0;      // 100000
    int E = in_sizes[1] / 2;       // 3200000
    int nb = (n + SCAN_BLK - 1) / SCAN_BLK;      // 98
    int e4blocks = ((E + 3) / 4 + 255) / 256;

    // Fork: CSR-build chain on s2, concurrent with gemm1 on the main stream.
    cudaEventRecord(evFork, 0);
    cudaStreamWaitEvent(s2, evFork, 0);

    zero_kernel<<<(n + 255) / 256, 256, 0, s2>>>(n);
    deg_kernel<<<e4blocks, 256, 0, s2>>>(ei, E);
    scan1_kernel<<<nb, SCAN_BLK, 0, s2>>>(n);
    scan3_kernel<<<(n + 255) / 256, 256, 0, s2>>>(n, E, nb);
    fill_kernel<<<(E + 255) / 256, 256, 0, s2>>>(ei, E);
    cudaEventRecord(evJoin, s2);

    gemm1_kernel<<<(n + GROWS - 1) / GROWS, 256>>>(x, W1, n);

    // Join: gathers need both hx (main) and csr/off/dinv (s2).
    cudaStreamWaitEvent(0, evJoin, 0);
    gather1_kernel<<<(n * 32 + 255) / 256, 256>>>(b1, n);
    gather2_kernel<<<(n + 7) / 8, 256>>>(Wm, bm, Wv, bv, out, n);
}

// round 12
// speedup vs baseline: 1.1725x; 1.0007x over previous
#include <cuda_runtime.h>
#include <cuda_fp16.h>

// Problem shape (fixed by dataset): 100000 nodes, 3.2M edges, 256 -> 32 -> 16x2
#define F0 256
#define F1 32
#define F2 16
#define MAXN 100000
#define MAXE 3200000
#define KT 32
#define GROWS 256
#define SCAN_BLK 1024
#define NBSUM 128         // >= nb = ceil(MAXN/SCAN_BLK) = 98

// Scratch (allocation-free rule: __device__ globals)
__device__ __align__(16) float  g_dinv[MAXN];
__device__ int    g_degcnt[MAXN];
__device__ int    g_off[MAXN + 1];
__device__ int    g_cursor[MAXN];
__device__ int    g_bsum[NBSUM];
__device__ __align__(16) float2 g_csr[MAXE];     // (src bits, weight)
__device__ __align__(16) __half g_hx16[MAXN * F1];   // x @ W1, fp16 storage
__device__ __align__(16) __half g_h16 [MAXN * F1];   // relu(layer-1), fp16

// ---------------------------------------------------------------------------
__global__ void zero_kernel(int n) {
    int i = blockIdx.x * blockDim.x + threadIdx.x;
    if (i < n) g_degcnt[i] = 0;
}

// in-degree over dst = edge_index[1], 4 edges per thread via int4
__global__ void deg_kernel(const int* __restrict__ ei, int E) {
    int e = (blockIdx.x * blockDim.x + threadIdx.x) * 4;
    if (e + 3 < E) {
        int4 d = *reinterpret_cast<const int4*>(ei + E + e);
        atomicAdd(&g_degcnt[d.x], 1);
        atomicAdd(&g_degcnt[d.y], 1);
        atomicAdd(&g_degcnt[d.z], 1);
        atomicAdd(&g_degcnt[d.w], 1);
    } else {
        for (int k = e; k < E; k++) atomicAdd(&g_degcnt[ei[E + k]], 1);
    }
}

// ---- scan1: per-block exclusive scan of degcnt (shuffle) + dinv -----------
__global__ void __launch_bounds__(SCAN_BLK) scan1_kernel(int n) {
    __shared__ int ws[32];
    int tid = threadIdx.x;
    int i = blockIdx.x * SCAN_BLK + tid;
    int lane = tid & 31, wid = tid >> 5;
    int v = (i < n) ? g_degcnt[i] : 0;
    if (i < n) g_dinv[i] = rsqrtf((float)v + 1.0f);
    int s = v;
#pragma unroll
    for (int o = 1; o < 32; o <<= 1) {
        int u = __shfl_up_sync(0xffffffffu, s, o);
        if (lane >= o) s += u;
    }
    if (lane == 31) ws[wid] = s;
    __syncthreads();
    if (wid == 0) {
        int t = ws[lane];
#pragma unroll
        for (int o = 1; o < 32; o <<= 1) {
            int u = __shfl_up_sync(0xffffffffu, t, o);
            if (lane >= o) t += u;
        }
        ws[lane] = t;
    }
    __syncthreads();
    int pre = wid ? ws[wid - 1] : 0;
    if (i < n) g_off[i] = s - v + pre;            // exclusive within block
    if (tid == 0) g_bsum[blockIdx.x] = ws[31];    // block total
}

// ---- scan3: redundant per-block scan of block sums + finalize offsets -----
__global__ void __launch_bounds__(256) scan3_kernel(int n, int E, int nb) {
    __shared__ int ws[8];
    __shared__ int sp[NBSUM];
    int tid = threadIdx.x;
    int lane = tid & 31, wid = tid >> 5;
    int v = (tid < nb) ? g_bsum[tid] : 0;
    int s = v;
#pragma unroll
    for (int o = 1; o < 32; o <<= 1) {
        int u = __shfl_up_sync(0xffffffffu, s, o);
        if (lane >= o) s += u;
    }
    if (lane == 31) ws[wid] = s;
    __syncthreads();
    if (wid == 0) {
        int t = (lane < 8) ? ws[lane] : 0;
#pragma unroll
        for (int o = 1; o < 8; o <<= 1) {
            int u = __shfl_up_sync(0xffffffffu, t, o);
            if (lane >= o) t += u;
        }
        if (lane < 8) ws[lane] = t;
    }
    __syncthreads();
    if (tid < nb) sp[tid] = s - v + (wid ? ws[wid - 1] : 0);  // exclusive
    __syncthreads();

    int i = blockIdx.x * 256 + tid;
    if (i < n) {
        int o = g_off[i] + sp[i >> 10];
        g_off[i] = o;
        g_cursor[i] = o;
    }
    if (i == 0) g_off[n] = E;
}

// ---- CSR fill: 1 edge per thread (proven round-3 config) ------------------
__global__ void fill_kernel(const int* __restrict__ ei, int E) {
    int e = blockIdx.x * blockDim.x + threadIdx.x;
    if (e >= E) return;
    int src = ei[e];
    int dst = ei[E + e];
    int pos = atomicAdd(&g_cursor[dst], 1);
    g_csr[pos] = make_float2(__int_as_float(src), g_dinv[src] * g_dinv[dst]);
}

// ---------------------------------------------------------------------------
// hx = x @ W1  (N x 256  @  256 x 32), register-tiled; fp16 pack epilogue.
__global__ void __launch_bounds__(256) gemm1_kernel(
        const float* __restrict__ x, const float* __restrict__ W1, int n) {
    __shared__ float xs[GROWS * (KT + 1)];
    __shared__ float Wts[KT * F1];

    int tid = threadIdx.x;
    int cg = tid & 3;
    int rg = tid >> 2;
    int row0 = blockIdx.x * GROWS;

    float acc[4][8];
#pragma unroll
    for (int i = 0; i < 4; i++)
#pragma unroll
        for (int j = 0; j < 8; j++) acc[i][j] = 0.0f;

    for (int kt = 0; kt < F0; kt += KT) {
        __syncthreads();
        {
            float4 w = *reinterpret_cast<const float4*>(W1 + (size_t)kt * F1 + tid * 4);
            *reinterpret_cast<float4*>(&Wts[tid * 4]) = w;
        }
#pragma unroll
        for (int it = 0; it < 8; it++) {
            int i = tid + it * 256;
            int r = i >> 3;
            int q = i & 7;
            int grow = row0 + r;
            float4 v = make_float4(0.f, 0.f, 0.f, 0.f);
            if (grow < n)
                v = *reinterpret_cast<const float4*>(x + (size_t)grow * F0 + kt + q * 4);
            float* dst = &xs[r * (KT + 1) + q * 4];
            dst[0] = v.x; dst[1] = v.y; dst[2] = v.z; dst[3] = v.w;
        }
        __syncthreads();

#pragma unroll
        for (int k = 0; k < KT; k++) {
            float xv[4];
#pragma unroll
            for (int i = 0; i < 4; i++)
                xv[i] = xs[(rg * 4 + i) * (KT + 1) + k];
            float4 w0 = *reinterpret_cast<const float4*>(&Wts[k * F1 + cg * 8]);
            float4 w1 = *reinterpret_cast<const float4*>(&Wts[k * F1 + cg * 8 + 4]);
#pragma unroll
            for (int i = 0; i < 4; i++) {
                acc[i][0] = fmaf(xv[i], w0.x, acc[i][0]);
                acc[i][1] = fmaf(xv[i], w0.y, acc[i][1]);
                acc[i][2] = fmaf(xv[i], w0.z, acc[i][2]);
                acc[i][3] = fmaf(xv[i], w0.w, acc[i][3]);
                acc[i][4] = fmaf(xv[i], w1.x, acc[i][4]);
                acc[i][5] = fmaf(xv[i], w1.y, acc[i][5]);
                acc[i][6] = fmaf(xv[i], w1.z, acc[i][6]);
                acc[i][7] = fmaf(xv[i], w1.w, acc[i][7]);
            }
        }
    }

#pragma unroll
    for (int i = 0; i < 4; i++) {
        int row = row0 + rg * 4 + i;
        if (row < n) {
            __half2 p[4];
            p[0] = __floats2half2_rn(acc[i][0], acc[i][1]);
            p[1] = __floats2half2_rn(acc[i][2], acc[i][3]);
            p[2] = __floats2half2_rn(acc[i][4], acc[i][5]);
            p[3] = __floats2half2_rn(acc[i][6], acc[i][7]);
            *reinterpret_cast<uint4*>(&g_hx16[(size_t)row * F1 + cg * 8]) =
                *reinterpret_cast<uint4*>(p);
        }
    }
}

// ---------------------------------------------------------------------------
// Gather core — proven round-3 inner loop, fp16 feature rows (64B/row).
__device__ __forceinline__ float gather_node(
        const __half* __restrict__ feat, int beg, int end, int lane) {
    float acc0 = 0.f, acc1 = 0.f;
    int k = beg;
    for (; k + 32 <= end; k += 32) {
        float2 rec = g_csr[k + lane];
        int   src = __float_as_int(rec.x);
        float w   = rec.y;
#pragma unroll
        for (int j = 0; j < 32; j += 2) {
            int   s0 = __shfl_sync(0xffffffffu, src, j);
            float w0 = __shfl_sync(0xffffffffu, w,   j);
            int   s1 = __shfl_sync(0xffffffffu, src, j + 1);
            float w1 = __shfl_sync(0xffffffffu, w,   j + 1);
            acc0 = fmaf(__half2float(feat[(size_t)s0 * F1 + lane]), w0, acc0);
            acc1 = fmaf(__half2float(feat[(size_t)s1 * F1 + lane]), w1, acc1);
        }
    }
    int rem = end - k;
    if (rem > 0) {
        float2 rec = make_float2(__int_as_float(0), 0.f);
        if (lane < rem) rec = g_csr[k + lane];
        int   src = __float_as_int(rec.x);
        float w   = rec.y;
        for (int j = 0; j < rem; j++) {
            int   s0 = __shfl_sync(0xffffffffu, src, j);
            float w0 = __shfl_sync(0xffffffffu, w,   j);
            acc0 = fmaf(__half2float(feat[(size_t)s0 * F1 + lane]), w0, acc0);
        }
    }
    return acc0 + acc1;
}

// Gather layer 1: one warp per node, lane = feature col.
__global__ void __launch_bounds__(256) gather1_kernel(
        const float* __restrict__ b1, int n) {
    int node = (blockIdx.x * blockDim.x + threadIdx.x) >> 5;
    int lane = threadIdx.x & 31;
    if (node >= n) return;
    int beg = g_off[node];
    int end = g_off[node + 1];
    float acc = gather_node(g_hx16, beg, end, lane);
    float d = g_dinv[node];
    float self = __half2float(g_hx16[(size_t)node * F1 + lane]);
    float v = acc + self * d * d + b1[lane];
    g_h16[(size_t)node * F1 + lane] = __float2half_rn(v > 0.f ? v : 0.f);
}

// Gather layer 2 + fused mu/sigma epilogue.
__global__ void __launch_bounds__(256) gather2_kernel(
        const float* __restrict__ Wm, const float* __restrict__ bm,
        const float* __restrict__ Wv, const float* __restrict__ bv,
        float* __restrict__ out, int n) {
    __shared__ float Wms[F1 * F2];
    __shared__ float Wvs[F1 * F2];
    __shared__ float ts[8][F1];
    for (int i = threadIdx.x; i < F1 * F2; i += blockDim.x) {
        Wms[i] = Wm[i];
        Wvs[i] = Wv[i];
    }
    __syncthreads();

    int wIn  = threadIdx.x >> 5;
    int lane = threadIdx.x & 31;
    int node = blockIdx.x * 8 + wIn;
    if (node >= n) return;

    int beg = g_off[node];
    int end = g_off[node + 1];
    float acc = gather_node(g_h16, beg, end, lane);
    float d = g_dinv[node];
    float self = __half2float(g_h16[(size_t)node * F1 + lane]);
    ts[wIn][lane] = acc + self * d * d;
    __syncwarp();

    int c = lane & 15;
    const float* Wp = (lane < 16) ? Wms : Wvs;
    float a = 0.f;
#pragma unroll
    for (int kk = 0; kk < F1; kk++)
        a = fmaf(ts[wIn][kk], Wp[kk * F2 + c], a);
    a += (lane < 16) ? bm[c] : bv[c];
    size_t o = (lane < 16) ? ((size_t)node * F2 + c)
                           : ((size_t)n * F2 + (size_t)node * F2 + c);
    out[o] = a;
}

// ---------------------------------------------------------------------------
extern "C" void kernel_launch(void* const* d_in, const int* in_sizes, int n_in,
                              void* d_out, int out_size) {
    // Lazily-created side stream + fork/join events (no device memory involved;
    // work issued is identical on every call -> deterministic & capturable).
    static cudaStream_t s2 = nullptr;
    static cudaEvent_t evFork = nullptr, evJoin = nullptr;
    if (s2 == nullptr) {
        cudaStreamCreateWithFlags(&s2, cudaStreamNonBlocking);
        cudaEventCreateWithFlags(&evFork, cudaEventDisableTiming);
        cudaEventCreateWithFlags(&evJoin, cudaEventDisableTiming);
    }

    const float* x  = (const float*)d_in[0];
    const int*   ei = (const int*)  d_in[1];
    const float* W1 = (const float*)d_in[2];
    const float* b1 = (const float*)d_in[3];
    const float* Wm = (const float*)d_in[4];
    const float* bm = (const float*)d_in[5];
    const float* Wv = (const float*)d_in[6];
    const float* bv = (const float*)d_in[7];
    float* out = (float*)d_out;

    int n = in_sizes[0] / F0;      // 100000
    int E = in_sizes[1] / 2;       // 3200000
    int nb = (n + SCAN_BLK - 1) / SCAN_BLK;      // 98
    int e4blocks = ((E + 3) / 4 + 255) / 256;

    // Fork: CSR-build chain on s2, concurrent with gemm1 on the main stream.
    cudaEventRecord(evFork, 0);
    cudaStreamWaitEvent(s2, evFork, 0);

    zero_kernel<<<(n + 255) / 256, 256, 0, s2>>>(n);
    deg_kernel<<<e4blocks, 256, 0, s2>>>(ei, E);
    scan1_kernel<<<nb, SCAN_BLK, 0, s2>>>(n);
    scan3_kernel<<<(n + 255) / 256, 256, 0, s2>>>(n, E, nb);
    fill_kernel<<<(E + 255) / 256, 256, 0, s2>>>(ei, E);
    cudaEventRecord(evJoin, s2);

    gemm1_kernel<<<(n + GROWS - 1) / GROWS, 256>>>(x, W1, n);

    // Join: gathers need both hx (main) and csr/off/dinv (s2).
    cudaStreamWaitEvent(0, evJoin, 0);
    gather1_kernel<<<(n * 32 + 255) / 256, 256>>>(b1, n);
    gather2_kernel<<<(n + 7) / 8, 256>>>(Wm, bm, Wv, bv, out, n);
}

// round 14
// speedup vs baseline: 1.3380x; 1.1411x over previous
#include <cuda_runtime.h>

// Problem shape (fixed by dataset): 100000 nodes, 3.2M edges, 256 -> 32 -> 16x2
#define F0 256
#define F1 32
#define F2 16
#define MAXN 100000
#define MAXE 3200000
#define KT 32
#define GROWS 256
#define SCAN_BLK 1024
#define NBSUM 128         // >= nb = ceil(MAXN/SCAN_BLK) = 98

// Scratch (allocation-free rule: __device__ globals)
__device__ __align__(16) float  g_dinv[MAXN];
__device__ int    g_degcnt[MAXN];
__device__ int    g_off[MAXN + 1];
__device__ int    g_cursor[MAXN];
__device__ int    g_bsum[NBSUM];
__device__ __align__(16) float2 g_csr[MAXE];     // (src bits, weight)
__device__ __align__(16) float  g_hx[MAXN * F1];
__device__ __align__(16) float  g_h [MAXN * F1];

// ---------------------------------------------------------------------------
__global__ void zero_kernel(int n) {
    int i = blockIdx.x * blockDim.x + threadIdx.x;
    if (i < n) g_degcnt[i] = 0;
}

// in-degree over dst = edge_index[1], 4 edges per thread via int4
__global__ void deg_kernel(const int* __restrict__ ei, int E) {
    int e = (blockIdx.x * blockDim.x + threadIdx.x) * 4;
    if (e + 3 < E) {
        int4 d = *reinterpret_cast<const int4*>(ei + E + e);
        atomicAdd(&g_degcnt[d.x], 1);
        atomicAdd(&g_degcnt[d.y], 1);
        atomicAdd(&g_degcnt[d.z], 1);
        atomicAdd(&g_degcnt[d.w], 1);
    } else {
        for (int k = e; k < E; k++) atomicAdd(&g_degcnt[ei[E + k]], 1);
    }
}

// ---- scan1: per-block exclusive scan of degcnt (shuffle) + dinv -----------
__global__ void __launch_bounds__(SCAN_BLK) scan1_kernel(int n) {
    __shared__ int ws[32];
    int tid = threadIdx.x;
    int i = blockIdx.x * SCAN_BLK + tid;
    int lane = tid & 31, wid = tid >> 5;
    int v = (i < n) ? g_degcnt[i] : 0;
    if (i < n) g_dinv[i] = rsqrtf((float)v + 1.0f);
    int s = v;
#pragma unroll
    for (int o = 1; o < 32; o <<= 1) {
        int u = __shfl_up_sync(0xffffffffu, s, o);
        if (lane >= o) s += u;
    }
    if (lane == 31) ws[wid] = s;
    __syncthreads();
    if (wid == 0) {
        int t = ws[lane];
#pragma unroll
        for (int o = 1; o < 32; o <<= 1) {
            int u = __shfl_up_sync(0xffffffffu, t, o);
            if (lane >= o) t += u;
        }
        ws[lane] = t;
    }
    __syncthreads();
    int pre = wid ? ws[wid - 1] : 0;
    if (i < n) g_off[i] = s - v + pre;            // exclusive within block
    if (tid == 0) g_bsum[blockIdx.x] = ws[31];    // block total
}

// ---- scan3: redundant per-block scan of block sums + finalize offsets -----
__global__ void __launch_bounds__(256) scan3_kernel(int n, int E, int nb) {
    __shared__ int ws[8];
    __shared__ int sp[NBSUM];
    int tid = threadIdx.x;
    int lane = tid & 31, wid = tid >> 5;
    int v = (tid < nb) ? g_bsum[tid] : 0;
    int s = v;
#pragma unroll
    for (int o = 1; o < 32; o <<= 1) {
        int u = __shfl_up_sync(0xffffffffu, s, o);
        if (lane >= o) s += u;
    }
    if (lane == 31) ws[wid] = s;
    __syncthreads();
    if (wid == 0) {
        int t = (lane < 8) ? ws[lane] : 0;
#pragma unroll
        for (int o = 1; o < 8; o <<= 1) {
            int u = __shfl_up_sync(0xffffffffu, t, o);
            if (lane >= o) t += u;
        }
        if (lane < 8) ws[lane] = t;
    }
    __syncthreads();
    if (tid < nb) sp[tid] = s - v + (wid ? ws[wid - 1] : 0);  // exclusive
    __syncthreads();

    int i = blockIdx.x * 256 + tid;
    if (i < n) {
        int o = g_off[i] + sp[i >> 10];
        g_off[i] = o;
        g_cursor[i] = o;
    }
    if (i == 0) g_off[n] = E;
}

// ---- CSR fill: 1 edge per thread (proven round-3 config) ------------------
__global__ void fill_kernel(const int* __restrict__ ei, int E) {
    int e = blockIdx.x * blockDim.x + threadIdx.x;
    if (e >= E) return;
    int src = ei[e];
    int dst = ei[E + e];
    int pos = atomicAdd(&g_cursor[dst], 1);
    g_csr[pos] = make_float2(__int_as_float(src), g_dinv[src] * g_dinv[dst]);
}

// ---------------------------------------------------------------------------
// hx = x @ W1  (N x 256  @  256 x 32), register-tiled (proven).
__global__ void __launch_bounds__(256) gemm1_kernel(
        const float* __restrict__ x, const float* __restrict__ W1, int n) {
    __shared__ float xs[GROWS * (KT + 1)];
    __shared__ float Wts[KT * F1];

    int tid = threadIdx.x;
    int cg = tid & 3;
    int rg = tid >> 2;
    int row0 = blockIdx.x * GROWS;

    float acc[4][8];
#pragma unroll
    for (int i = 0; i < 4; i++)
#pragma unroll
        for (int j = 0; j < 8; j++) acc[i][j] = 0.0f;

    for (int kt = 0; kt < F0; kt += KT) {
        __syncthreads();
        {
            float4 w = *reinterpret_cast<const float4*>(W1 + (size_t)kt * F1 + tid * 4);
            *reinterpret_cast<float4*>(&Wts[tid * 4]) = w;
        }
#pragma unroll
        for (int it = 0; it < 8; it++) {
            int i = tid + it * 256;
            int r = i >> 3;
            int q = i & 7;
            int grow = row0 + r;
            float4 v = make_float4(0.f, 0.f, 0.f, 0.f);
            if (grow < n)
                v = *reinterpret_cast<const float4*>(x + (size_t)grow * F0 + kt + q * 4);
            float* dst = &xs[r * (KT + 1) + q * 4];
            dst[0] = v.x; dst[1] = v.y; dst[2] = v.z; dst[3] = v.w;
        }
        __syncthreads();

#pragma unroll
        for (int k = 0; k < KT; k++) {
            float xv[4];
#pragma unroll
            for (int i = 0; i < 4; i++)
                xv[i] = xs[(rg * 4 + i) * (KT + 1) + k];
            float4 w0 = *reinterpret_cast<const float4*>(&Wts[k * F1 + cg * 8]);
            float4 w1 = *reinterpret_cast<const float4*>(&Wts[k * F1 + cg * 8 + 4]);
#pragma unroll
            for (int i = 0; i < 4; i++) {
                acc[i][0] = fmaf(xv[i], w0.x, acc[i][0]);
                acc[i][1] = fmaf(xv[i], w0.y, acc[i][1]);
                acc[i][2] = fmaf(xv[i], w0.z, acc[i][2]);
                acc[i][3] = fmaf(xv[i], w0.w, acc[i][3]);
                acc[i][4] = fmaf(xv[i], w1.x, acc[i][4]);
                acc[i][5] = fmaf(xv[i], w1.y, acc[i][5]);
                acc[i][6] = fmaf(xv[i], w1.z, acc[i][6]);
                acc[i][7] = fmaf(xv[i], w1.w, acc[i][7]);
            }
        }
    }

#pragma unroll
    for (int i = 0; i < 4; i++) {
        int row = row0 + rg * 4 + i;
        if (row < n) {
            float* dst = &g_hx[(size_t)row * F1 + cg * 8];
            *reinterpret_cast<float4*>(dst) =
                make_float4(acc[i][0], acc[i][1], acc[i][2], acc[i][3]);
            *reinterpret_cast<float4*>(dst + 4) =
                make_float4(acc[i][4], acc[i][5], acc[i][6], acc[i][7]);
        }
    }
}

// ---------------------------------------------------------------------------
// Gather core v2 — 2 nodes per warp. Lanes 0-15 = node A, 16-31 = node B.
// Each lane owns 2 feature cols (float2). Per step: 1 warp-LDG covers 2 edges
// (one row per half-warp); shfl width=16 broadcasts each half's own (src,w).
// Tiles of 16 records, zero-padded, static 16-step unroll; both halves run
// max(tilesA, tilesB) so the full-mask shfls stay converged.
__device__ __forceinline__ float2 gather_node2(
        const float* __restrict__ feat, int beg, int end, int hl) {
    float2 acc = make_float2(0.f, 0.f);
    int myTiles = (end - beg + 15) >> 4;
    int otherTiles = __shfl_xor_sync(0xffffffffu, myTiles, 16);
    int tiles = myTiles > otherTiles ? myTiles : otherTiles;
    for (int t = 0; t < tiles; t++) {
        int k = beg + t * 16;
        int cnt = end - k;                   // may be <= 0 (pure pad tile)
        float2 rec = make_float2(__int_as_float(0), 0.f);
        if (hl < cnt) rec = g_csr[k + hl];
        int   src = __float_as_int(rec.x);
        float w   = rec.y;
#pragma unroll
        for (int j = 0; j < 16; j++) {
            int   s  = __shfl_sync(0xffffffffu, src, j, 16);
            float ww = __shfl_sync(0xffffffffu, w,   j, 16);
            float2 f = *reinterpret_cast<const float2*>(
                &feat[(size_t)s * F1 + 2 * hl]);
            acc.x = fmaf(f.x, ww, acc.x);
            acc.y = fmaf(f.y, ww, acc.y);
        }
    }
    return acc;
}

// Gather layer 1: 2 nodes per warp.
__global__ void __launch_bounds__(256) gather1_kernel(
        const float* __restrict__ b1, int n) {
    int warp = (blockIdx.x * blockDim.x + threadIdx.x) >> 5;
    int lane = threadIdx.x & 31;
    int half = lane >> 4;
    int hl   = lane & 15;
    int node = warp * 2 + half;
    bool valid = node < n;
    int nodeC = valid ? node : (n - 1);          // clamp; keep warp converged
    int beg = g_off[nodeC];
    int end = g_off[nodeC + 1];
    float2 acc = gather_node2(g_hx, beg, end, hl);
    float d = g_dinv[nodeC];
    float2 self = *reinterpret_cast<const float2*>(
        &g_hx[(size_t)nodeC * F1 + 2 * hl]);
    float vx = acc.x + self.x * d * d + b1[2 * hl];
    float vy = acc.y + self.y * d * d + b1[2 * hl + 1];
    if (valid) {
        float2 o;
        o.x = vx > 0.f ? vx : 0.f;
        o.y = vy > 0.f ? vy : 0.f;
        *reinterpret_cast<float2*>(&g_h[(size_t)node * F1 + 2 * hl]) = o;
    }
}

// Gather layer 2 + fused mu/sigma epilogue: 2 nodes per warp.
__global__ void __launch_bounds__(256) gather2_kernel(
        const float* __restrict__ Wm, const float* __restrict__ bm,
        const float* __restrict__ Wv, const float* __restrict__ bv,
        float* __restrict__ out, int n) {
    __shared__ float Wms[F1 * F2];
    __shared__ float Wvs[F1 * F2];
    __shared__ float ts[8][2][F1];
    for (int i = threadIdx.x; i < F1 * F2; i += blockDim.x) {
        Wms[i] = Wm[i];
        Wvs[i] = Wv[i];
    }
    __syncthreads();

    int wIn  = threadIdx.x >> 5;
    int lane = threadIdx.x & 31;
    int half = lane >> 4;
    int hl   = lane & 15;
    int warp = blockIdx.x * 8 + wIn;
    int node = warp * 2 + half;
    bool valid = node < n;
    int nodeC = valid ? node : (n - 1);

    int beg = g_off[nodeC];
    int end = g_off[nodeC + 1];
    float2 acc = gather_node2(g_h, beg, end, hl);
    float d = g_dinv[nodeC];
    float2 self = *reinterpret_cast<const float2*>(
        &g_h[(size_t)nodeC * F1 + 2 * hl]);
    ts[wIn][half][2 * hl]     = acc.x + self.x * d * d;
    ts[wIn][half][2 * hl + 1] = acc.y + self.y * d * d;
    __syncwarp();

    // epilogue: each lane produces mu[node][hl] and sigma[node][hl]
    float am = 0.f, av = 0.f;
#pragma unroll
    for (int kk = 0; kk < F1; kk++) {
        float t = ts[wIn][half][kk];
        am = fmaf(t, Wms[kk * F2 + hl], am);
        av = fmaf(t, Wvs[kk * F2 + hl], av);
    }
    if (valid) {
        out[(size_t)node * F2 + hl]                  = am + bm[hl];
        out[(size_t)n * F2 + (size_t)node * F2 + hl] = av + bv[hl];
    }
}

// ---------------------------------------------------------------------------
extern "C" void kernel_launch(void* const* d_in, const int* in_sizes, int n_in,
                              void* d_out, int out_size) {
    // Lazily-created side stream + fork/join events (no device memory involved;
    // work issued is identical on every call -> deterministic & capturable).
    static cudaStream_t s2 = nullptr;
    static cudaEvent_t evFork = nullptr, evJoin = nullptr;
    if (s2 == nullptr) {
        cudaStreamCreateWithFlags(&s2, cudaStreamNonBlocking);
        cudaEventCreateWithFlags(&evFork, cudaEventDisableTiming);
        cudaEventCreateWithFlags(&evJoin, cudaEventDisableTiming);
    }

    const float* x  = (const float*)d_in[0];
    const int*   ei = (const int*)  d_in[1];
    const float* W1 = (const float*)d_in[2];
    const float* b1 = (const float*)d_in[3];
    const float* Wm = (const float*)d_in[4];
    const float* bm = (const float*)d_in[5];
    const float* Wv = (const float*)d_in[6];
    const float* bv = (const float*)d_in[7];
    float* out = (float*)d_out;

    int n = in_sizes[0] / F0;      // 100000
    int E = in_sizes[1] / 2;       // 3200000
    int nb = (n + SCAN_BLK - 1) / SCAN_BLK;      // 98
    int e4blocks = ((E + 3) / 4 + 255) / 256;
    int nwarps = (n + 1) / 2;                    // 2 nodes per warp
    int gblocks = (nwarps * 32 + 255) / 256;

    // Fork: CSR-build chain on s2, concurrent with gemm1 on the main stream.
    cudaEventRecord(evFork, 0);
    cudaStreamWaitEvent(s2, evFork, 0);

    zero_kernel<<<(n + 255) / 256, 256, 0, s2>>>(n);
    deg_kernel<<<e4blocks, 256, 0, s2>>>(ei, E);
    scan1_kernel<<<nb, SCAN_BLK, 0, s2>>>(n);
    scan3_kernel<<<(n + 255) / 256, 256, 0, s2>>>(n, E, nb);
    fill_kernel<<<(E + 255) / 256, 256, 0, s2>>>(ei, E);
    cudaEventRecord(evJoin, s2);

    gemm1_kernel<<<(n + GROWS - 1) / GROWS, 256>>>(x, W1, n);

    // Join: gathers need both hx (main) and csr/off/dinv (s2).
    cudaStreamWaitEvent(0, evJoin, 0);
    gather1_kernel<<<gblocks, 256>>>(b1, n);
    gather2_kernel<<<gblocks, 256>>>(Wm, bm, Wv, bv, out, n);
}

// round 16
// speedup vs baseline: 1.3572x; 1.0144x over previous
#include <cuda_runtime.h>

// Problem shape (fixed by dataset): 100000 nodes, 3.2M edges, 256 -> 32 -> 16x2
#define F0 256
#define F1 32
#define F2 16
#define MAXN 100000
#define MAXE 3200000
#define KT 32
#define GROWS 256
#define SCAN_BLK 1024
#define NBSUM 128         // >= nb = ceil(MAXN/SCAN_BLK) = 98

// Scratch (allocation-free rule: __device__ globals)
__device__ __align__(16) float  g_dinv[MAXN];
__device__ int    g_degcnt[MAXN];
__device__ int    g_off[MAXN + 1];
__device__ int    g_cursor[MAXN];
__device__ int    g_bsum[NBSUM];
__device__ __align__(16) float2 g_csr[MAXE];     // (src bits, weight)
__device__ __align__(16) float  g_hx[MAXN * F1];
__device__ __align__(16) float  g_h [MAXN * F1];

// ---------------------------------------------------------------------------
__global__ void zero_kernel(int n) {
    int i = blockIdx.x * blockDim.x + threadIdx.x;
    if (i < n) g_degcnt[i] = 0;
}

// in-degree over dst = edge_index[1], 4 edges per thread via int4
__global__ void deg_kernel(const int* __restrict__ ei, int E) {
    int e = (blockIdx.x * blockDim.x + threadIdx.x) * 4;
    if (e + 3 < E) {
        int4 d = *reinterpret_cast<const int4*>(ei + E + e);
        atomicAdd(&g_degcnt[d.x], 1);
        atomicAdd(&g_degcnt[d.y], 1);
        atomicAdd(&g_degcnt[d.z], 1);
        atomicAdd(&g_degcnt[d.w], 1);
    } else {
        for (int k = e; k < E; k++) atomicAdd(&g_degcnt[ei[E + k]], 1);
    }
}

// ---- scan1: per-block exclusive scan of degcnt (shuffle) + dinv -----------
__global__ void __launch_bounds__(SCAN_BLK) scan1_kernel(int n) {
    __shared__ int ws[32];
    int tid = threadIdx.x;
    int i = blockIdx.x * SCAN_BLK + tid;
    int lane = tid & 31, wid = tid >> 5;
    int v = (i < n) ? g_degcnt[i] : 0;
    if (i < n) g_dinv[i] = rsqrtf((float)v + 1.0f);
    int s = v;
#pragma unroll
    for (int o = 1; o < 32; o <<= 1) {
        int u = __shfl_up_sync(0xffffffffu, s, o);
        if (lane >= o) s += u;
    }
    if (lane == 31) ws[wid] = s;
    __syncthreads();
    if (wid == 0) {
        int t = ws[lane];
#pragma unroll
        for (int o = 1; o < 32; o <<= 1) {
            int u = __shfl_up_sync(0xffffffffu, t, o);
            if (lane >= o) t += u;
        }
        ws[lane] = t;
    }
    __syncthreads();
    int pre = wid ? ws[wid - 1] : 0;
    if (i < n) g_off[i] = s - v + pre;            // exclusive within block
    if (tid == 0) g_bsum[blockIdx.x] = ws[31];    // block total
}

// ---- scan3: redundant per-block scan of block sums + finalize offsets -----
__global__ void __launch_bounds__(256) scan3_kernel(int n, int E, int nb) {
    __shared__ int ws[8];
    __shared__ int sp[NBSUM];
    int tid = threadIdx.x;
    int lane = tid & 31, wid = tid >> 5;
    int v = (tid < nb) ? g_bsum[tid] : 0;
    int s = v;
#pragma unroll
    for (int o = 1; o < 32; o <<= 1) {
        int u = __shfl_up_sync(0xffffffffu, s, o);
        if (lane >= o) s += u;
    }
    if (lane == 31) ws[wid] = s;
    __syncthreads();
    if (wid == 0) {
        int t = (lane < 8) ? ws[lane] : 0;
#pragma unroll
        for (int o = 1; o < 8; o <<= 1) {
            int u = __shfl_up_sync(0xffffffffu, t, o);
            if (lane >= o) t += u;
        }
        if (lane < 8) ws[lane] = t;
    }
    __syncthreads();
    if (tid < nb) sp[tid] = s - v + (wid ? ws[wid - 1] : 0);  // exclusive
    __syncthreads();

    int i = blockIdx.x * 256 + tid;
    if (i < n) {
        int o = g_off[i] + sp[i >> 10];
        g_off[i] = o;
        g_cursor[i] = o;
    }
    if (i == 0) g_off[n] = E;
}

// ---- CSR fill: 1 edge per thread (proven round-3 config) ------------------
__global__ void fill_kernel(const int* __restrict__ ei, int E) {
    int e = blockIdx.x * blockDim.x + threadIdx.x;
    if (e >= E) return;
    int src = ei[e];
    int dst = ei[E + e];
    int pos = atomicAdd(&g_cursor[dst], 1);
    g_csr[pos] = make_float2(__int_as_float(src), g_dinv[src] * g_dinv[dst]);
}

// ---------------------------------------------------------------------------
// hx = x @ W1  (N x 256  @  256 x 32), register-tiled (proven).
__global__ void __launch_bounds__(256) gemm1_kernel(
        const float* __restrict__ x, const float* __restrict__ W1, int n) {
    __shared__ float xs[GROWS * (KT + 1)];
    __shared__ float Wts[KT * F1];

    int tid = threadIdx.x;
    int cg = tid & 3;
    int rg = tid >> 2;
    int row0 = blockIdx.x * GROWS;

    float acc[4][8];
#pragma unroll
    for (int i = 0; i < 4; i++)
#pragma unroll
        for (int j = 0; j < 8; j++) acc[i][j] = 0.0f;

    for (int kt = 0; kt < F0; kt += KT) {
        __syncthreads();
        {
            float4 w = *reinterpret_cast<const float4*>(W1 + (size_t)kt * F1 + tid * 4);
            *reinterpret_cast<float4*>(&Wts[tid * 4]) = w;
        }
#pragma unroll
        for (int it = 0; it < 8; it++) {
            int i = tid + it * 256;
            int r = i >> 3;
            int q = i & 7;
            int grow = row0 + r;
            float4 v = make_float4(0.f, 0.f, 0.f, 0.f);
            if (grow < n)
                v = *reinterpret_cast<const float4*>(x + (size_t)grow * F0 + kt + q * 4);
            float* dst = &xs[r * (KT + 1) + q * 4];
            dst[0] = v.x; dst[1] = v.y; dst[2] = v.z; dst[3] = v.w;
        }
        __syncthreads();

#pragma unroll
        for (int k = 0; k < KT; k++) {
            float xv[4];
#pragma unroll
            for (int i = 0; i < 4; i++)
                xv[i] = xs[(rg * 4 + i) * (KT + 1) + k];
            float4 w0 = *reinterpret_cast<const float4*>(&Wts[k * F1 + cg * 8]);
            float4 w1 = *reinterpret_cast<const float4*>(&Wts[k * F1 + cg * 8 + 4]);
#pragma unroll
            for (int i = 0; i < 4; i++) {
                acc[i][0] = fmaf(xv[i], w0.x, acc[i][0]);
                acc[i][1] = fmaf(xv[i], w0.y, acc[i][1]);
                acc[i][2] = fmaf(xv[i], w0.z, acc[i][2]);
                acc[i][3] = fmaf(xv[i], w0.w, acc[i][3]);
                acc[i][4] = fmaf(xv[i], w1.x, acc[i][4]);
                acc[i][5] = fmaf(xv[i], w1.y, acc[i][5]);
                acc[i][6] = fmaf(xv[i], w1.z, acc[i][6]);
                acc[i][7] = fmaf(xv[i], w1.w, acc[i][7]);
            }
        }
    }

#pragma unroll
    for (int i = 0; i < 4; i++) {
        int row = row0 + rg * 4 + i;
        if (row < n) {
            float* dst = &g_hx[(size_t)row * F1 + cg * 8];
            *reinterpret_cast<float4*>(dst) =
                make_float4(acc[i][0], acc[i][1], acc[i][2], acc[i][3]);
            *reinterpret_cast<float4*>(dst + 4) =
                make_float4(acc[i][4], acc[i][5], acc[i][6], acc[i][7]);
        }
    }
}

// ---------------------------------------------------------------------------
// Gather core v3 — 4 nodes per warp. Subgroup = 8 lanes per node; each lane
// owns 4 feature cols (float4; 8 lanes x 16B = full 128B row). Per j-step one
// warp-LDG covers 4 edges (one row per subgroup); shfl width=8 broadcasts each
// subgroup's own (src,w). Tiles of 8 records, zero-padded, static 8-step
// unroll; all subgroups run max(tiles) so full-mask shfls stay converged.
__device__ __forceinline__ float4 gather_node4(
        const float* __restrict__ feat, int beg, int end, int hl) {
    float4 acc = make_float4(0.f, 0.f, 0.f, 0.f);
    int myTiles = (end - beg + 7) >> 3;
    int o1 = __shfl_xor_sync(0xffffffffu, myTiles, 8);
    int m1 = myTiles > o1 ? myTiles : o1;
    int o2 = __shfl_xor_sync(0xffffffffu, m1, 16);
    int tiles = m1 > o2 ? m1 : o2;
    for (int t = 0; t < tiles; t++) {
        int k = beg + t * 8;
        int cnt = end - k;                   // may be <= 0 (pure pad tile)
        float2 rec = make_float2(__int_as_float(0), 0.f);
        if (hl < cnt) rec = g_csr[k + hl];
        int   src = __float_as_int(rec.x);
        float w   = rec.y;
#pragma unroll
        for (int j = 0; j < 8; j++) {
            int   s  = __shfl_sync(0xffffffffu, src, j, 8);
            float ww = __shfl_sync(0xffffffffu, w,   j, 8);
            float4 f = *reinterpret_cast<const float4*>(
                &feat[(size_t)s * F1 + 4 * hl]);
            acc.x = fmaf(f.x, ww, acc.x);
            acc.y = fmaf(f.y, ww, acc.y);
            acc.z = fmaf(f.z, ww, acc.z);
            acc.w = fmaf(f.w, ww, acc.w);
        }
    }
    return acc;
}

// Gather layer 1: 4 nodes per warp.
__global__ void __launch_bounds__(256) gather1_kernel(
        const float* __restrict__ b1, int n) {
    int warp = (blockIdx.x * blockDim.x + threadIdx.x) >> 5;
    int lane = threadIdx.x & 31;
    int sub  = lane >> 3;            // 0..3
    int hl   = lane & 7;             // 0..7
    int node = warp * 4 + sub;
    bool valid = node < n;
    int nodeC = valid ? node : (n - 1);          // clamp; keep warp converged
    int beg = g_off[nodeC];
    int end = g_off[nodeC + 1];
    float4 acc = gather_node4(g_hx, beg, end, hl);
    float d = g_dinv[nodeC];
    float d2 = d * d;
    float4 self = *reinterpret_cast<const float4*>(
        &g_hx[(size_t)nodeC * F1 + 4 * hl]);
    float4 o;
    o.x = acc.x + self.x * d2 + b1[4 * hl];
    o.y = acc.y + self.y * d2 + b1[4 * hl + 1];
    o.z = acc.z + self.z * d2 + b1[4 * hl + 2];
    o.w = acc.w + self.w * d2 + b1[4 * hl + 3];
    o.x = o.x > 0.f ? o.x : 0.f;
    o.y = o.y > 0.f ? o.y : 0.f;
    o.z = o.z > 0.f ? o.z : 0.f;
    o.w = o.w > 0.f ? o.w : 0.f;
    if (valid)
        *reinterpret_cast<float4*>(&g_h[(size_t)node * F1 + 4 * hl]) = o;
}

// Gather layer 2 + fused mu/sigma epilogue: 4 nodes per warp.
__global__ void __launch_bounds__(256) gather2_kernel(
        const float* __restrict__ Wm, const float* __restrict__ bm,
        const float* __restrict__ Wv, const float* __restrict__ bv,
        float* __restrict__ out, int n) {
    __shared__ float Wms[F1 * F2];
    __shared__ float Wvs[F1 * F2];
    __shared__ float ts[8][4][F1];
    for (int i = threadIdx.x; i < F1 * F2; i += blockDim.x) {
        Wms[i] = Wm[i];
        Wvs[i] = Wv[i];
    }
    __syncthreads();

    int wIn  = threadIdx.x >> 5;
    int lane = threadIdx.x & 31;
    int sub  = lane >> 3;
    int hl   = lane & 7;
    int warp = blockIdx.x * 8 + wIn;
    int node = warp * 4 + sub;
    bool valid = node < n;
    int nodeC = valid ? node : (n - 1);

    int beg = g_off[nodeC];
    int end = g_off[nodeC + 1];
    float4 acc = gather_node4(g_h, beg, end, hl);
    float d = g_dinv[nodeC];
    float d2 = d * d;
    float4 self = *reinterpret_cast<const float4*>(
        &g_h[(size_t)nodeC * F1 + 4 * hl]);
    ts[wIn][sub][4 * hl]     = acc.x + self.x * d2;
    ts[wIn][sub][4 * hl + 1] = acc.y + self.y * d2;
    ts[wIn][sub][4 * hl + 2] = acc.z + self.z * d2;
    ts[wIn][sub][4 * hl + 3] = acc.w + self.w * d2;
    __syncwarp();

    // epilogue: 8 lanes per node; each lane produces mu cols {2hl, 2hl+1}
    // and sigma cols {2hl, 2hl+1} for its node.
    int c0 = 2 * hl, c1 = 2 * hl + 1;
    float am0 = 0.f, am1 = 0.f, av0 = 0.f, av1 = 0.f;
#pragma unroll
    for (int kk = 0; kk < F1; kk++) {
        float t = ts[wIn][sub][kk];
        am0 = fmaf(t, Wms[kk * F2 + c0], am0);
        am1 = fmaf(t, Wms[kk * F2 + c1], am1);
        av0 = fmaf(t, Wvs[kk * F2 + c0], av0);
        av1 = fmaf(t, Wvs[kk * F2 + c1], av1);
    }
    if (valid) {
        float2 om = make_float2(am0 + bm[c0], am1 + bm[c1]);
        float2 ov = make_float2(av0 + bv[c0], av1 + bv[c1]);
        *reinterpret_cast<float2*>(&out[(size_t)node * F2 + c0]) = om;
        *reinterpret_cast<float2*>(
            &out[(size_t)n * F2 + (size_t)node * F2 + c0]) = ov;
    }
}

// ---------------------------------------------------------------------------
extern "C" void kernel_launch(void* const* d_in, const int* in_sizes, int n_in,
                              void* d_out, int out_size) {
    // Lazily-created side stream + fork/join events (no device memory involved;
    // work issued is identical on every call -> deterministic & capturable).
    static cudaStream_t s2 = nullptr;
    static cudaEvent_t evFork = nullptr, evJoin = nullptr;
    if (s2 == nullptr) {
        cudaStreamCreateWithFlags(&s2, cudaStreamNonBlocking);
        cudaEventCreateWithFlags(&evFork, cudaEventDisableTiming);
        cudaEventCreateWithFlags(&evJoin, cudaEventDisableTiming);
    }

    const float* x  = (const float*)d_in[0];
    const int*   ei = (const int*)  d_in[1];
    const float* W1 = (const float*)d_in[2];
    const float* b1 = (const float*)d_in[3];
    const float* Wm = (const float*)d_in[4];
    const float* bm = (const float*)d_in[5];
    const float* Wv = (const float*)d_in[6];
    const float* bv = (const float*)d_in[7];
    float* out = (float*)d_out;

    int n = in_sizes[0] / F0;      // 100000
    int E = in_sizes[1] / 2;       // 3200000
    int nb = (n + SCAN_BLK - 1) / SCAN_BLK;      // 98
    int e4blocks = ((E + 3) / 4 + 255) / 256;
    int nwarps = (n + 3) / 4;                    // 4 nodes per warp
    int gblocks = (nwarps * 32 + 255) / 256;

    // Fork: CSR-build chain on s2, concurrent with gemm1 on the main stream.
    cudaEventRecord(evFork, 0);
    cudaStreamWaitEvent(s2, evFork, 0);

    zero_kernel<<<(n + 255) / 256, 256, 0, s2>>>(n);
    deg_kernel<<<e4blocks, 256, 0, s2>>>(ei, E);
    scan1_kernel<<<nb, SCAN_BLK, 0, s2>>>(n);
    scan3_kernel<<<(n + 255) / 256, 256, 0, s2>>>(n, E, nb);
    fill_kernel<<<(E + 255) / 256, 256, 0, s2>>>(ei, E);
    cudaEventRecord(evJoin, s2);

    gemm1_kernel<<<(n + GROWS - 1) / GROWS, 256>>>(x, W1, n);

    // Join: gathers need both hx (main) and csr/off/dinv (s2).
    cudaStreamWaitEvent(0, evJoin, 0);
    gather1_kernel<<<gblocks, 256>>>(b1, n);
    gather2_kernel<<<gblocks, 256>>>(Wm, bm, Wv, bv, out, n);
}

// round 17
// speedup vs baseline: 1.5124x; 1.1143x over previous
#include <cuda_runtime.h>
#include <cuda_fp16.h>

// Problem shape (fixed by dataset): 100000 nodes, 3.2M edges, 256 -> 32 -> 16x2
#define F0 256
#define F1 32
#define F2 16
#define MAXN 100000
#define MAXE 3200000
#define KT 32
#define GROWS 256
#define SCAN_BLK 1024
#define NBSUM 128         // >= nb = ceil(MAXN/SCAN_BLK) = 98

// Scratch (allocation-free rule: __device__ globals)
__device__ __align__(16) float  g_dinv[MAXN];
__device__ int    g_degcnt[MAXN];
__device__ int    g_off[MAXN + 1];
__device__ int    g_cursor[MAXN];
__device__ int    g_bsum[NBSUM];
__device__ __align__(16) float2 g_csr[MAXE];     // (src bits, weight)
__device__ __align__(16) __half g_hx16[MAXN * F1];   // x @ W1, fp16 storage
__device__ __align__(16) __half g_h16 [MAXN * F1];   // relu(layer-1), fp16

// ---------------------------------------------------------------------------
__global__ void zero_kernel(int n) {
    int i = blockIdx.x * blockDim.x + threadIdx.x;
    if (i < n) g_degcnt[i] = 0;
}

// in-degree over dst = edge_index[1], 4 edges per thread via int4
__global__ void deg_kernel(const int* __restrict__ ei, int E) {
    int e = (blockIdx.x * blockDim.x + threadIdx.x) * 4;
    if (e + 3 < E) {
        int4 d = *reinterpret_cast<const int4*>(ei + E + e);
        atomicAdd(&g_degcnt[d.x], 1);
        atomicAdd(&g_degcnt[d.y], 1);
        atomicAdd(&g_degcnt[d.z], 1);
        atomicAdd(&g_degcnt[d.w], 1);
    } else {
        for (int k = e; k < E; k++) atomicAdd(&g_degcnt[ei[E + k]], 1);
    }
}

// ---- scan1: per-block exclusive scan of degcnt (shuffle) + dinv -----------
__global__ void __launch_bounds__(SCAN_BLK) scan1_kernel(int n) {
    __shared__ int ws[32];
    int tid = threadIdx.x;
    int i = blockIdx.x * SCAN_BLK + tid;
    int lane = tid & 31, wid = tid >> 5;
    int v = (i < n) ? g_degcnt[i] : 0;
    if (i < n) g_dinv[i] = rsqrtf((float)v + 1.0f);
    int s = v;
#pragma unroll
    for (int o = 1; o < 32; o <<= 1) {
        int u = __shfl_up_sync(0xffffffffu, s, o);
        if (lane >= o) s += u;
    }
    if (lane == 31) ws[wid] = s;
    __syncthreads();
    if (wid == 0) {
        int t = ws[lane];
#pragma unroll
        for (int o = 1; o < 32; o <<= 1) {
            int u = __shfl_up_sync(0xffffffffu, t, o);
            if (lane >= o) t += u;
        }
        ws[lane] = t;
    }
    __syncthreads();
    int pre = wid ? ws[wid - 1] : 0;
    if (i < n) g_off[i] = s - v + pre;            // exclusive within block
    if (tid == 0) g_bsum[blockIdx.x] = ws[31];    // block total
}

// ---- scan3: redundant per-block scan of block sums + finalize offsets -----
__global__ void __launch_bounds__(256) scan3_kernel(int n, int E, int nb) {
    __shared__ int ws[8];
    __shared__ int sp[NBSUM];
    int tid = threadIdx.x;
    int lane = tid & 31, wid = tid >> 5;
    int v = (tid < nb) ? g_bsum[tid] : 0;
    int s = v;
#pragma unroll
    for (int o = 1; o < 32; o <<= 1) {
        int u = __shfl_up_sync(0xffffffffu, s, o);
        if (lane >= o) s += u;
    }
    if (lane == 31) ws[wid] = s;
    __syncthreads();
    if (wid == 0) {
        int t = (lane < 8) ? ws[lane] : 0;
#pragma unroll
        for (int o = 1; o < 8; o <<= 1) {
            int u = __shfl_up_sync(0xffffffffu, t, o);
            if (lane >= o) t += u;
        }
        if (lane < 8) ws[lane] = t;
    }
    __syncthreads();
    if (tid < nb) sp[tid] = s - v + (wid ? ws[wid - 1] : 0);  // exclusive
    __syncthreads();

    int i = blockIdx.x * 256 + tid;
    if (i < n) {
        int o = g_off[i] + sp[i >> 10];
        g_off[i] = o;
        g_cursor[i] = o;
    }
    if (i == 0) g_off[n] = E;
}

// ---- CSR fill: 1 edge per thread (proven round-3 config) ------------------
__global__ void fill_kernel(const int* __restrict__ ei, int E) {
    int e = blockIdx.x * blockDim.x + threadIdx.x;
    if (e >= E) return;
    int src = ei[e];
    int dst = ei[E + e];
    int pos = atomicAdd(&g_cursor[dst], 1);
    g_csr[pos] = make_float2(__int_as_float(src), g_dinv[src] * g_dinv[dst]);
}

// ---------------------------------------------------------------------------
// hx = x @ W1  (N x 256  @  256 x 32), register-tiled; fp16 pack epilogue.
__global__ void __launch_bounds__(256) gemm1_kernel(
        const float* __restrict__ x, const float* __restrict__ W1, int n) {
    __shared__ float xs[GROWS * (KT + 1)];
    __shared__ float Wts[KT * F1];

    int tid = threadIdx.x;
    int cg = tid & 3;
    int rg = tid >> 2;
    int row0 = blockIdx.x * GROWS;

    float acc[4][8];
#pragma unroll
    for (int i = 0; i < 4; i++)
#pragma unroll
        for (int j = 0; j < 8; j++) acc[i][j] = 0.0f;

    for (int kt = 0; kt < F0; kt += KT) {
        __syncthreads();
        {
            float4 w = *reinterpret_cast<const float4*>(W1 + (size_t)kt * F1 + tid * 4);
            *reinterpret_cast<float4*>(&Wts[tid * 4]) = w;
        }
#pragma unroll
        for (int it = 0; it < 8; it++) {
            int i = tid + it * 256;
            int r = i >> 3;
            int q = i & 7;
            int grow = row0 + r;
            float4 v = make_float4(0.f, 0.f, 0.f, 0.f);
            if (grow < n)
                v = *reinterpret_cast<const float4*>(x + (size_t)grow * F0 + kt + q * 4);
            float* dst = &xs[r * (KT + 1) + q * 4];
            dst[0] = v.x; dst[1] = v.y; dst[2] = v.z; dst[3] = v.w;
        }
        __syncthreads();

#pragma unroll
        for (int k = 0; k < KT; k++) {
            float xv[4];
#pragma unroll
            for (int i = 0; i < 4; i++)
                xv[i] = xs[(rg * 4 + i) * (KT + 1) + k];
            float4 w0 = *reinterpret_cast<const float4*>(&Wts[k * F1 + cg * 8]);
            float4 w1 = *reinterpret_cast<const float4*>(&Wts[k * F1 + cg * 8 + 4]);
#pragma unroll
            for (int i = 0; i < 4; i++) {
                acc[i][0] = fmaf(xv[i], w0.x, acc[i][0]);
                acc[i][1] = fmaf(xv[i], w0.y, acc[i][1]);
                acc[i][2] = fmaf(xv[i], w0.z, acc[i][2]);
                acc[i][3] = fmaf(xv[i], w0.w, acc[i][3]);
                acc[i][4] = fmaf(xv[i], w1.x, acc[i][4]);
                acc[i][5] = fmaf(xv[i], w1.y, acc[i][5]);
                acc[i][6] = fmaf(xv[i], w1.z, acc[i][6]);
                acc[i][7] = fmaf(xv[i], w1.w, acc[i][7]);
            }
        }
    }

#pragma unroll
    for (int i = 0; i < 4; i++) {
        int row = row0 + rg * 4 + i;
        if (row < n) {
            __half2 p[4];
            p[0] = __floats2half2_rn(acc[i][0], acc[i][1]);
            p[1] = __floats2half2_rn(acc[i][2], acc[i][3]);
            p[2] = __floats2half2_rn(acc[i][4], acc[i][5]);
            p[3] = __floats2half2_rn(acc[i][6], acc[i][7]);
            *reinterpret_cast<uint4*>(&g_hx16[(size_t)row * F1 + cg * 8]) =
                *reinterpret_cast<uint4*>(p);
        }
    }
}

// ---------------------------------------------------------------------------
// Gather core v4 — 4 nodes per warp, fp16 feature rows (64B/row).
// Subgroup = 8 lanes per node; each lane owns 4 cols (8B = uint2 of half2).
// Per j-step one warp-LDG covers 4 rows x 64B = 2 lines (half of fp32).
__device__ __forceinline__ float4 gather_node4(
        const __half* __restrict__ feat, int beg, int end, int hl) {
    float4 acc = make_float4(0.f, 0.f, 0.f, 0.f);
    int myTiles = (end - beg + 7) >> 3;
    int o1 = __shfl_xor_sync(0xffffffffu, myTiles, 8);
    int m1 = myTiles > o1 ? myTiles : o1;
    int o2 = __shfl_xor_sync(0xffffffffu, m1, 16);
    int tiles = m1 > o2 ? m1 : o2;
    for (int t = 0; t < tiles; t++) {
        int k = beg + t * 8;
        int cnt = end - k;                   // may be <= 0 (pure pad tile)
        float2 rec = make_float2(__int_as_float(0), 0.f);
        if (hl < cnt) rec = g_csr[k + hl];
        int   src = __float_as_int(rec.x);
        float w   = rec.y;
#pragma unroll
        for (int j = 0; j < 8; j++) {
            int   s  = __shfl_sync(0xffffffffu, src, j, 8);
            float ww = __shfl_sync(0xffffffffu, w,   j, 8);
            uint2 raw = *reinterpret_cast<const uint2*>(
                &feat[(size_t)s * F1 + 4 * hl]);
            float2 f01 = __half22float2(*reinterpret_cast<__half2*>(&raw.x));
            float2 f23 = __half22float2(*reinterpret_cast<__half2*>(&raw.y));
            acc.x = fmaf(f01.x, ww, acc.x);
            acc.y = fmaf(f01.y, ww, acc.y);
            acc.z = fmaf(f23.x, ww, acc.z);
            acc.w = fmaf(f23.y, ww, acc.w);
        }
    }
    return acc;
}

// Gather layer 1: 4 nodes per warp, fp16 in/out.
__global__ void __launch_bounds__(256) gather1_kernel(
        const float* __restrict__ b1, int n) {
    int warp = (blockIdx.x * blockDim.x + threadIdx.x) >> 5;
    int lane = threadIdx.x & 31;
    int sub  = lane >> 3;            // 0..3
    int hl   = lane & 7;             // 0..7
    int node = warp * 4 + sub;
    bool valid = node < n;
    int nodeC = valid ? node : (n - 1);          // clamp; keep warp converged
    int beg = g_off[nodeC];
    int end = g_off[nodeC + 1];
    float4 acc = gather_node4(g_hx16, beg, end, hl);
    float d = g_dinv[nodeC];
    float d2 = d * d;
    uint2 raw = *reinterpret_cast<const uint2*>(
        &g_hx16[(size_t)nodeC * F1 + 4 * hl]);
    float2 s01 = __half22float2(*reinterpret_cast<__half2*>(&raw.x));
    float2 s23 = __half22float2(*reinterpret_cast<__half2*>(&raw.y));
    float ox = acc.x + s01.x * d2 + b1[4 * hl];
    float oy = acc.y + s01.y * d2 + b1[4 * hl + 1];
    float oz = acc.z + s23.x * d2 + b1[4 * hl + 2];
    float ow = acc.w + s23.y * d2 + b1[4 * hl + 3];
    ox = ox > 0.f ? ox : 0.f;
    oy = oy > 0.f ? oy : 0.f;
    oz = oz > 0.f ? oz : 0.f;
    ow = ow > 0.f ? ow : 0.f;
    if (valid) {
        __half2 p0 = __floats2half2_rn(ox, oy);
        __half2 p1 = __floats2half2_rn(oz, ow);
        uint2 packed;
        packed.x = *reinterpret_cast<unsigned*>(&p0);
        packed.y = *reinterpret_cast<unsigned*>(&p1);
        *reinterpret_cast<uint2*>(&g_h16[(size_t)node * F1 + 4 * hl]) = packed;
    }
}

// Gather layer 2 + fused mu/sigma epilogue: 4 nodes per warp.
__global__ void __launch_bounds__(256) gather2_kernel(
        const float* __restrict__ Wm, const float* __restrict__ bm,
        const float* __restrict__ Wv, const float* __restrict__ bv,
        float* __restrict__ out, int n) {
    __shared__ float Wms[F1 * F2];
    __shared__ float Wvs[F1 * F2];
    __shared__ float ts[8][4][F1];
    for (int i = threadIdx.x; i < F1 * F2; i += blockDim.x) {
        Wms[i] = Wm[i];
        Wvs[i] = Wv[i];
    }
    __syncthreads();

    int wIn  = threadIdx.x >> 5;
    int lane = threadIdx.x & 31;
    int sub  = lane >> 3;
    int hl   = lane & 7;
    int warp = blockIdx.x * 8 + wIn;
    int node = warp * 4 + sub;
    bool valid = node < n;
    int nodeC = valid ? node : (n - 1);

    int beg = g_off[nodeC];
    int end = g_off[nodeC + 1];
    float4 acc = gather_node4(g_h16, beg, end, hl);
    float d = g_dinv[nodeC];
    float d2 = d * d;
    uint2 raw = *reinterpret_cast<const uint2*>(
        &g_h16[(size_t)nodeC * F1 + 4 * hl]);
    float2 s01 = __half22float2(*reinterpret_cast<__half2*>(&raw.x));
    float2 s23 = __half22float2(*reinterpret_cast<__half2*>(&raw.y));
    ts[wIn][sub][4 * hl]     = acc.x + s01.x * d2;
    ts[wIn][sub][4 * hl + 1] = acc.y + s01.y * d2;
    ts[wIn][sub][4 * hl + 2] = acc.z + s23.x * d2;
    ts[wIn][sub][4 * hl + 3] = acc.w + s23.y * d2;
    __syncwarp();

    // epilogue: 8 lanes per node; each lane produces mu cols {2hl, 2hl+1}
    // and sigma cols {2hl, 2hl+1} for its node.
    int c0 = 2 * hl, c1 = 2 * hl + 1;
    float am0 = 0.f, am1 = 0.f, av0 = 0.f, av1 = 0.f;
#pragma unroll
    for (int kk = 0; kk < F1; kk++) {
        float t = ts[wIn][sub][kk];
        am0 = fmaf(t, Wms[kk * F2 + c0], am0);
        am1 = fmaf(t, Wms[kk * F2 + c1], am1);
        av0 = fmaf(t, Wvs[kk * F2 + c0], av0);
        av1 = fmaf(t, Wvs[kk * F2 + c1], av1);
    }
    if (valid) {
        float2 om = make_float2(am0 + bm[c0], am1 + bm[c1]);
        float2 ov = make_float2(av0 + bv[c0], av1 + bv[c1]);
        *reinterpret_cast<float2*>(&out[(size_t)node * F2 + c0]) = om;
        *reinterpret_cast<float2*>(
            &out[(size_t)n * F2 + (size_t)node * F2 + c0]) = ov;
    }
}

// ---------------------------------------------------------------------------
extern "C" void kernel_launch(void* const* d_in, const int* in_sizes, int n_in,
                              void* d_out, int out_size) {
    // Lazily-created side stream + fork/join events (no device memory involved;
    // work issued is identical on every call -> deterministic & capturable).
    static cudaStream_t s2 = nullptr;
    static cudaEvent_t evFork = nullptr, evJoin = nullptr;
    if (s2 == nullptr) {
        cudaStreamCreateWithFlags(&s2, cudaStreamNonBlocking);
        cudaEventCreateWithFlags(&evFork, cudaEventDisableTiming);
        cudaEventCreateWithFlags(&evJoin, cudaEventDisableTiming);
    }

    const float* x  = (const float*)d_in[0];
    const int*   ei = (const int*)  d_in[1];
    const float* W1 = (const float*)d_in[2];
    const float* b1 = (const float*)d_in[3];
    const float* Wm = (const float*)d_in[4];
    const float* bm = (const float*)d_in[5];
    const float* Wv = (const float*)d_in[6];
    const float* bv = (const float*)d_in[7];
    float* out = (float*)d_out;

    int n = in_sizes[0] / F0;      // 100000
    int E = in_sizes[1] / 2;       // 3200000
    int nb = (n + SCAN_BLK - 1) / SCAN_BLK;      // 98
    int e4blocks = ((E + 3) / 4 + 255) / 256;
    int nwarps = (n + 3) / 4;                    // 4 nodes per warp
    int gblocks = (nwarps * 32 + 255) / 256;

    // Fork: CSR-build chain on s2, concurrent with gemm1 on the main stream.
    cudaEventRecord(evFork, 0);
    cudaStreamWaitEvent(s2, evFork, 0);

    zero_kernel<<<(n + 255) / 256, 256, 0, s2>>>(n);
    deg_kernel<<<e4blocks, 256, 0, s2>>>(ei, E);
    scan1_kernel<<<nb, SCAN_BLK, 0, s2>>>(n);
    scan3_kernel<<<(n + 255) / 256, 256, 0, s2>>>(n, E, nb);
    fill_kernel<<<(E + 255) / 256, 256, 0, s2>>>(ei, E);
    cudaEventRecord(evJoin, s2);

    gemm1_kernel<<<(n + GROWS - 1) / GROWS, 256>>>(x, W1, n);

    // Join: gathers need both hx (main) and csr/off/dinv (s2).
    cudaStreamWaitEvent(0, evJoin, 0);
    gather1_kernel<<<gblocks, 256>>>(b1, n);
    gather2_kernel<<<gblocks, 256>>>(Wm, bm, Wv, bv, out, n);
}